// round 1
// baseline (speedup 1.0000x reference)
#include <cuda_runtime.h>
#include <math.h>
#include <float.h>

#define Bz 2
#define Sz 2048
#define Dz 512
#define Hz 8
#define DPH 64
#define BH (Bz*Hz)
#define Mrows (Bz*Sz)

// scratch: projected q (as qm: time negated), k, v in (b,h,s,d) layout; softmax row stats
__device__ float g_q[(size_t)BH*Sz*DPH];
__device__ float g_k[(size_t)BH*Sz*DPH];
__device__ float g_v[(size_t)BH*Sz*DPH];
__device__ float g_m[BH*Sz];
__device__ float g_l[BH*Sz];

// ---------------------------------------------------------------------------
// Projection + Lorentz epilogue.  y = X @ W^T + b  (M=4096, N=512, K=512)
// BN=64 == one head chunk -> per-row space-norm reduction stays in-block.
// ---------------------------------------------------------------------------
__global__ __launch_bounds__(256) void proj_kernel(
    const float* __restrict__ X, const float* __restrict__ W,
    const float* __restrict__ bias, const float* __restrict__ lsc,
    int which, int negate)
{
    float* out = (which == 0) ? g_q : (which == 1) ? g_k : g_v;

    __shared__ float As[16][65];
    __shared__ float Bs[16][65];
    __shared__ float red[64][17];
    __shared__ float timeSh[64];

    const int tid = threadIdx.x;
    const int tx = tid & 15, ty = tid >> 4;
    const int n0 = blockIdx.x * 64;
    const int m0 = blockIdx.y * 64;

    const int lr = tid >> 2;        // 0..63 row within tile
    const int lk = (tid & 3) * 4;   // 0,4,8,12 k-offset

    float acc[4][4];
#pragma unroll
    for (int i = 0; i < 4; i++)
#pragma unroll
        for (int j = 0; j < 4; j++) acc[i][j] = 0.f;

    for (int k0 = 0; k0 < Dz; k0 += 16) {
        float4 av = *reinterpret_cast<const float4*>(X + (size_t)(m0 + lr) * Dz + k0 + lk);
        float4 bv = *reinterpret_cast<const float4*>(W + (size_t)(n0 + lr) * Dz + k0 + lk);
        As[lk + 0][lr] = av.x; As[lk + 1][lr] = av.y; As[lk + 2][lr] = av.z; As[lk + 3][lr] = av.w;
        Bs[lk + 0][lr] = bv.x; Bs[lk + 1][lr] = bv.y; Bs[lk + 2][lr] = bv.z; Bs[lk + 3][lr] = bv.w;
        __syncthreads();
#pragma unroll
        for (int kk = 0; kk < 16; kk++) {
            float a[4], b[4];
#pragma unroll
            for (int i = 0; i < 4; i++) a[i] = As[kk][ty * 4 + i];
#pragma unroll
            for (int j = 0; j < 4; j++) b[j] = Bs[kk][tx * 4 + j];
#pragma unroll
            for (int i = 0; i < 4; i++)
#pragma unroll
                for (int j = 0; j < 4; j++) acc[i][j] = fmaf(a[i], b[j], acc[i][j]);
        }
        __syncthreads();
    }

    const float es = expf(lsc[0]);

    float y[4][4];
#pragma unroll
    for (int i = 0; i < 4; i++) {
        float p = 0.f;
#pragma unroll
        for (int j = 0; j < 4; j++) {
            int c = tx * 4 + j;
            float yy = acc[i][j] + bias[n0 + c];
            y[i][j] = yy;
            if (c != 0) p = fmaf(yy, yy, p);
        }
        red[ty * 4 + i][tx] = p;
    }
    __syncthreads();
    if (tx == 0) {
#pragma unroll
        for (int i = 0; i < 4; i++) {
            float t = 1.f / (1.f + expf(-y[i][0])) * es + 1.1f;
            timeSh[ty * 4 + i] = t;
        }
    }
    __syncthreads();

    const int h = n0 / 64;
#pragma unroll
    for (int i = 0; i < 4; i++) {
        int r = ty * 4 + i;
        float sq = 0.f;
#pragma unroll
        for (int u = 0; u < 16; u++) sq += red[r][u];
        sq = fmaxf(sq, 1e-8f);
        float t = timeSh[r];
        float f = sqrtf((t * t - 1.f) / sq);
        int m = m0 + r;
        int b = m / Sz, s = m % Sz;
        float* orow = out + (size_t)((b * Hz + h) * Sz + s) * DPH;
#pragma unroll
        for (int j = 0; j < 4; j++) {
            int c = tx * 4 + j;
            float o = (c == 0) ? (negate ? -t : t) : y[i][j] * f;
            orow[c] = o;
        }
    }
}

// ---------------------------------------------------------------------------
// Scores: raw score write + online (max, sumexp) per row.  Causal tiles only.
// ---------------------------------------------------------------------------
__global__ __launch_bounds__(256) void scores_kernel(
    float* __restrict__ attn,
    const float* __restrict__ scale_ptr, const float* __restrict__ bias_ptr)
{
    const int bh = blockIdx.y, qt = blockIdx.x;
    const int tid = threadIdx.x, tx = tid & 15, ty = tid >> 4;

    __shared__ float Qs[64][65];
    __shared__ float Ks[64][65];
    __shared__ float red[64][17];

    const float* Qg = g_q + (size_t)bh * Sz * DPH + (size_t)qt * 64 * DPH;
#pragma unroll
    for (int it = 0; it < 4; ++it) {
        int idx = tid + it * 256;
        int q = idx >> 4;
        int d4 = (idx & 15) * 4;
        float4 v = *reinterpret_cast<const float4*>(Qg + q * DPH + d4);
        Qs[d4 + 0][q] = v.x; Qs[d4 + 1][q] = v.y; Qs[d4 + 2][q] = v.z; Qs[d4 + 3][q] = v.w;
    }

    const float inv_as = 1.f / scale_ptr[0];
    const float ab = bias_ptr[0];

    float m_run[4], l_run[4];
#pragma unroll
    for (int i = 0; i < 4; i++) { m_run[i] = -FLT_MAX; l_run[i] = 0.f; }

    const float* Kg = g_k + (size_t)bh * Sz * DPH;
    float* arow = attn + (size_t)bh * Sz * Sz;

    for (int kt = 0; kt <= qt; ++kt) {
        __syncthreads();
#pragma unroll
        for (int it = 0; it < 4; ++it) {
            int idx = tid + it * 256;
            int r = idx >> 4;
            int d4 = (idx & 15) * 4;
            float4 v = *reinterpret_cast<const float4*>(Kg + (size_t)(kt * 64 + r) * DPH + d4);
            Ks[d4 + 0][r] = v.x; Ks[d4 + 1][r] = v.y; Ks[d4 + 2][r] = v.z; Ks[d4 + 3][r] = v.w;
        }
        __syncthreads();

        float acc[4][4];
#pragma unroll
        for (int i = 0; i < 4; i++)
#pragma unroll
            for (int j = 0; j < 4; j++) acc[i][j] = 0.f;
#pragma unroll
        for (int kk = 0; kk < 64; kk++) {
            float a[4], b[4];
#pragma unroll
            for (int i = 0; i < 4; i++) a[i] = Qs[kk][ty * 4 + i];
#pragma unroll
            for (int j = 0; j < 4; j++) b[j] = Ks[kk][tx * 4 + j];
#pragma unroll
            for (int i = 0; i < 4; i++)
#pragma unroll
                for (int j = 0; j < 4; j++) acc[i][j] = fmaf(a[i], b[j], acc[i][j]);
        }

        float sreg[4][4];
#pragma unroll
        for (int i = 0; i < 4; i++) {
            int gq = qt * 64 + ty * 4 + i;
#pragma unroll
            for (int j = 0; j < 4; j++) {
                int gk = kt * 64 + tx * 4 + j;
                float s = (2.f + 2.f * acc[i][j]) * inv_as + ab;
                if (gk > gq) s = -FLT_MAX;   // masked; overwritten with 0 in pass B
                sreg[i][j] = s;
            }
            float4 sv = make_float4(sreg[i][0], sreg[i][1], sreg[i][2], sreg[i][3]);
            *reinterpret_cast<float4*>(arow + (size_t)gq * Sz + kt * 64 + tx * 4) = sv;
        }

        // online stats
#pragma unroll
        for (int i = 0; i < 4; i++) {
            float pm = fmaxf(fmaxf(sreg[i][0], sreg[i][1]), fmaxf(sreg[i][2], sreg[i][3]));
            red[ty * 4 + i][tx] = pm;
        }
        __syncthreads();
        float newm[4];
#pragma unroll
        for (int i = 0; i < 4; i++) {
            float tm = -FLT_MAX;
#pragma unroll
            for (int u = 0; u < 16; u++) tm = fmaxf(tm, red[ty * 4 + i][u]);
            newm[i] = fmaxf(m_run[i], tm);
        }
        __syncthreads();
#pragma unroll
        for (int i = 0; i < 4; i++) {
            float pl = 0.f;
#pragma unroll
            for (int j = 0; j < 4; j++) pl += expf(sreg[i][j] - newm[i]);
            red[ty * 4 + i][tx] = pl;
        }
        __syncthreads();
#pragma unroll
        for (int i = 0; i < 4; i++) {
            float tl = 0.f;
#pragma unroll
            for (int u = 0; u < 16; u++) tl += red[ty * 4 + i][u];
            l_run[i] = l_run[i] * expf(m_run[i] - newm[i]) + tl;
            m_run[i] = newm[i];
        }
    }

    if (tx == 0) {
#pragma unroll
        for (int i = 0; i < 4; i++) {
            int gq = qt * 64 + ty * 4 + i;
            g_m[bh * Sz + gq] = m_run[i];
            g_l[bh * Sz + gq] = l_run[i];
        }
    }
}

// ---------------------------------------------------------------------------
// Normalize attn (incl. zeroing upper triangle) + attn@V + Lorentz context.
// ---------------------------------------------------------------------------
__global__ __launch_bounds__(256) void av_kernel(
    float* __restrict__ attn, float* __restrict__ ctx)
{
    const int bh = blockIdx.y, qt = blockIdx.x;
    const int b = bh / Hz, h = bh % Hz;
    const int tid = threadIdx.x, tx = tid & 15, ty = tid >> 4;

    __shared__ float Ps[64][65];   // [k][q] normalized probabilities
    __shared__ float Vs[64][65];   // [k][d]
    __shared__ float red[64][17];
    __shared__ float msh[64], ilsh[64];

    if (tid < 64) {
        msh[tid] = g_m[bh * Sz + qt * 64 + tid];
        ilsh[tid] = 1.f / g_l[bh * Sz + qt * 64 + tid];
    }

    float acc[4][4];
#pragma unroll
    for (int i = 0; i < 4; i++)
#pragma unroll
        for (int j = 0; j < 4; j++) acc[i][j] = 0.f;

    float* arow = attn + (size_t)bh * Sz * Sz;
    const float* Vg = g_v + (size_t)bh * Sz * DPH;

    const int NKT = Sz / 64;
    for (int kt = 0; kt < NKT; ++kt) {
        const bool live = (kt <= qt);
        __syncthreads();
#pragma unroll
        for (int it = 0; it < 4; ++it) {
            int idx = tid + it * 256;
            int q = idx >> 4;
            int c4 = (idx & 15) * 4;
            int gq = qt * 64 + q;
            size_t off = (size_t)gq * Sz + kt * 64 + c4;
            float4 p = make_float4(0.f, 0.f, 0.f, 0.f);
            if (live) {
                float4 s = *reinterpret_cast<const float4*>(arow + off);
                float mm = msh[q], il = ilsh[q];
                int gk = kt * 64 + c4;
                p.x = (gk + 0 <= gq) ? expf(s.x - mm) * il : 0.f;
                p.y = (gk + 1 <= gq) ? expf(s.y - mm) * il : 0.f;
                p.z = (gk + 2 <= gq) ? expf(s.z - mm) * il : 0.f;
                p.w = (gk + 3 <= gq) ? expf(s.w - mm) * il : 0.f;
                Ps[c4 + 0][q] = p.x; Ps[c4 + 1][q] = p.y;
                Ps[c4 + 2][q] = p.z; Ps[c4 + 3][q] = p.w;
            }
            *reinterpret_cast<float4*>(arow + off) = p;   // final attn (0 above diag)
        }
        if (live) {
#pragma unroll
            for (int it = 0; it < 4; ++it) {
                int idx = tid + it * 256;
                int r = idx >> 4;
                int d4 = (idx & 15) * 4;
                float4 v = *reinterpret_cast<const float4*>(Vg + (size_t)(kt * 64 + r) * DPH + d4);
                Vs[r][d4 + 0] = v.x; Vs[r][d4 + 1] = v.y; Vs[r][d4 + 2] = v.z; Vs[r][d4 + 3] = v.w;
            }
        }
        __syncthreads();
        if (live) {
#pragma unroll
            for (int kk = 0; kk < 64; kk++) {
                float p[4], v[4];
#pragma unroll
                for (int i = 0; i < 4; i++) p[i] = Ps[kk][ty * 4 + i];
#pragma unroll
                for (int j = 0; j < 4; j++) v[j] = Vs[kk][tx * 4 + j];
#pragma unroll
                for (int i = 0; i < 4; i++)
#pragma unroll
                    for (int j = 0; j < 4; j++) acc[i][j] = fmaf(p[i], v[j], acc[i][j]);
            }
        }
    }

    // Lorentz context normalization: inner = -ave0^2 + sum(ave_rest^2)
#pragma unroll
    for (int i = 0; i < 4; i++) {
        float pp = 0.f;
#pragma unroll
        for (int j = 0; j < 4; j++) {
            int d = tx * 4 + j;
            float a = acc[i][j];
            pp += (d == 0) ? -a * a : a * a;
        }
        red[ty * 4 + i][tx] = pp;
    }
    __syncthreads();
#pragma unroll
    for (int i = 0; i < 4; i++) {
        int r = ty * 4 + i;
        float inner = 0.f;
#pragma unroll
        for (int u = 0; u < 16; u++) inner += red[r][u];
        float denom = sqrtf(fmaxf(fabsf(inner), 1e-8f));
        float inv = 1.f / denom;
        int gq = qt * 64 + r;
        float* crow = ctx + (size_t)((b * Sz + gq) * Hz + h) * DPH + tx * 4;
#pragma unroll
        for (int j = 0; j < 4; j++) crow[j] = acc[i][j] * inv;
    }
}

extern "C" void kernel_launch(void* const* d_in, const int* in_sizes, int n_in,
                              void* d_out, int out_size)
{
    const float* key   = (const float*)d_in[0];
    const float* value = (const float*)d_in[1];
    const float* query = (const float*)d_in[2];
    // d_in[3] = mask (strict upper triangle); applied analytically by index.
    const float* Wq = (const float*)d_in[4];
    const float* bq = (const float*)d_in[5];
    const float* sq = (const float*)d_in[6];
    const float* Wk = (const float*)d_in[7];
    const float* bk = (const float*)d_in[8];
    const float* sk = (const float*)d_in[9];
    const float* Wv = (const float*)d_in[10];
    const float* bv = (const float*)d_in[11];
    const float* sv = (const float*)d_in[12];
    const float* att_scale = (const float*)d_in[13];
    const float* att_bias  = (const float*)d_in[14];

    float* ctx  = (float*)d_out;
    float* attn = ctx + (size_t)Bz * Sz * Dz;   // output tuple: (context, attn)

    dim3 gp(Dz / 64, Mrows / 64);
    proj_kernel<<<gp, 256>>>(query, Wq, bq, sq, 0, 1);  // store qm (time negated)
    proj_kernel<<<gp, 256>>>(key,   Wk, bk, sk, 1, 0);
    proj_kernel<<<gp, 256>>>(value, Wv, bv, sv, 2, 0);

    dim3 ga(Sz / 64, BH);
    scores_kernel<<<ga, 256>>>(attn, att_scale, att_bias);
    av_kernel<<<ga, 256>>>(attn, ctx);
}